// round 13
// baseline (speedup 1.0000x reference)
#include <cuda_runtime.h>
#include <cuda_fp16.h>
#include <mma.h>
#include <cstdint>

using namespace nvcuda;

// GCN: out = GCNConv2( relu(GCNConv1(x)) )
// H = x@W1 (raw, fp16) — NO dinv, so gemm1 has no dependency on the CSR chain
// and overlaps it fully via fork-join capture.
// agg1: x1 = relu(dinv[d]*(sum_{s in N(d)+self} dinv[s]*H[s]) + b1)  (fp16)
// gemm2: Hs2 = dinv * (x1 @ W2) (fp16);  agg2: out = dinv*(Hs2[d]+gather) + b2

#define N_NODES 100000
#define N_EDGES 1600000
#define EMB 128
#define HID 128
#define RPR 64
#define SCAN_BLOCKS 391   // ceil(100000/256)

// ---------------- scratch (device globals, allocation-free) ----------------
__device__ float  g_dinv[N_NODES];
__device__ __half g_H  [(long long)N_NODES * HID];   // layer1 raw hidden (fp16)
__device__ __half g_X1h[(long long)N_NODES * HID];   // relu(conv1) output (fp16)
__device__ __half g_Hs2[(long long)N_NODES * RPR];   // layer2 scaled hidden (fp16)
__device__ int    g_cnt[N_NODES];
__device__ int    g_rowptr[N_NODES];                  // start; end = start + cnt
__device__ int    g_cur[N_NODES];
__device__ int    g_total;
__device__ int    g_adj[N_EDGES];

// ---------------- helpers ----------------
__device__ __forceinline__ unsigned int h2u(float a, float b) {
    __half2 h = __floats2half2_rn(a, b);
    return *reinterpret_cast<unsigned int*>(&h);
}
__device__ __forceinline__ float2 u2f(unsigned int u) {
    __half2 h = *reinterpret_cast<__half2*>(&u);
    return __half22float2(h);
}

// ---------------- CSR build + degree ----------------
__global__ void k_zero() {
    int i = blockIdx.x * blockDim.x + threadIdx.x;
    if (i < N_NODES) g_cnt[i] = 0;
    if (i == 0) g_total = 0;
}

// 4 edges per iteration: 4 independent ATOMGs in flight per thread
__global__ void k_hist(const int* __restrict__ dst) {
    int stride = gridDim.x * blockDim.x;
    const int4* d4 = (const int4*)dst;
    for (int e = blockIdx.x * blockDim.x + threadIdx.x; e < N_EDGES / 4; e += stride) {
        int4 d = __ldg(d4 + e);
        atomicAdd(&g_cnt[d.x], 1);
        atomicAdd(&g_cnt[d.y], 1);
        atomicAdd(&g_cnt[d.z], 1);
        atomicAdd(&g_cnt[d.w], 1);
    }
}

// single-kernel scan: block prefix sum + atomic base (rowptr need not be
// globally monotonic; agg uses end = rowptr + cnt)
__global__ void k_scan() {
    __shared__ int sh[256];
    __shared__ int base;
    int t = threadIdx.x;
    int i = blockIdx.x * 256 + t;
    int v = (i < N_NODES) ? g_cnt[i] : 0;
    sh[t] = v;
    __syncthreads();
    for (int off = 1; off < 256; off <<= 1) {
        int add = 0;
        if (t >= off) add = sh[t - off];
        __syncthreads();
        sh[t] += add;
        __syncthreads();
    }
    if (t == 255) base = atomicAdd(&g_total, sh[255]);
    __syncthreads();
    int excl = base + sh[t] - v;
    if (i < N_NODES) {
        g_rowptr[i] = excl;
        g_cur[i]    = excl;
        g_dinv[i]   = rsqrtf(1.0f + (float)v);   // +1 for self loop
    }
}

// 4 edges per iteration
__global__ void k_fill(const int* __restrict__ src, const int* __restrict__ dst) {
    int stride = gridDim.x * blockDim.x;
    const int4* s4 = (const int4*)src;
    const int4* d4 = (const int4*)dst;
    for (int e = blockIdx.x * blockDim.x + threadIdx.x; e < N_EDGES / 4; e += stride) {
        int4 s = __ldg(s4 + e);
        int4 d = __ldg(d4 + e);
        int p0 = atomicAdd(&g_cur[d.x], 1);
        int p1 = atomicAdd(&g_cur[d.y], 1);
        int p2 = atomicAdd(&g_cur[d.z], 1);
        int p3 = atomicAdd(&g_cur[d.w], 1);
        g_adj[p0] = s.x;
        g_adj[p1] = s.y;
        g_adj[p2] = s.z;
        g_adj[p3] = s.w;
    }
}

// ---------------- layer-1 GEMM (tensor cores): H = x @ W1 (raw), fp16 out ----
// No dinv dependency -> runs concurrently with the whole CSR build.
#define LDA1 136
#define LDC1 132
__global__ __launch_bounds__(256)
void k_gemm1_tc(const float* __restrict__ x, const float* __restrict__ W1) {
    extern __shared__ char dynsmem[];
    __half* A_h = (__half*)dynsmem;                 // [128][136]
    __half* B_h = A_h + 128 * LDA1;                 // [128][136]
    float*  C_f = (float*)dynsmem;                  // [128][132] (reuse after mma)

    const int tid  = threadIdx.x;
    const int warp = tid >> 5;
    const int rowBase = blockIdx.x * 128;

    // fill B: W1 fp32 -> fp16 (128x128), pairs
    for (int idx = tid; idx < 128 * 64; idx += 256) {
        int k = idx >> 6, n2 = idx & 63;
        float2 w = *(const float2*)&W1[k * HID + n2 * 2];
        *(unsigned int*)&B_h[k * LDA1 + n2 * 2] = h2u(w.x, w.y);
    }
    // fill A: x tile fp32 -> fp16, zero-pad invalid rows
    for (int idx = tid; idx < 128 * 32; idx += 256) {
        int r = idx >> 5, q4 = idx & 31;
        int gr = rowBase + r;
        unsigned int p0 = 0, p1 = 0;
        if (gr < N_NODES) {
            float4 v = *(const float4*)&x[(size_t)gr * EMB + q4 * 4];
            p0 = h2u(v.x, v.y);
            p1 = h2u(v.z, v.w);
        }
        *(unsigned int*)&A_h[r * LDA1 + q4 * 4]     = p0;
        *(unsigned int*)&A_h[r * LDA1 + q4 * 4 + 2] = p1;
    }
    __syncthreads();

    wmma::fragment<wmma::accumulator, 16, 16, 16, float> acc[8];
#pragma unroll
    for (int n = 0; n < 8; n++) wmma::fill_fragment(acc[n], 0.0f);

#pragma unroll
    for (int k = 0; k < 8; k++) {
        wmma::fragment<wmma::matrix_a, 16, 16, 16, __half, wmma::row_major> a;
        wmma::load_matrix_sync(a, &A_h[warp * 16 * LDA1 + k * 16], LDA1);
#pragma unroll
        for (int n = 0; n < 8; n++) {
            wmma::fragment<wmma::matrix_b, 16, 16, 16, __half, wmma::row_major> b;
            wmma::load_matrix_sync(b, &B_h[k * 16 * LDA1 + n * 16], LDA1);
            wmma::mma_sync(acc[n], a, b, acc[n]);
        }
    }
    __syncthreads();   // done reading A/B smem; reuse as C staging

#pragma unroll
    for (int n = 0; n < 8; n++)
        wmma::store_matrix_sync(&C_f[warp * 16 * LDC1 + n * 16], acc[n], LDC1,
                                wmma::mem_row_major);
    __syncthreads();

    // epilogue: convert fp16 (no scaling), write. 2 threads/row, 64 cols each.
    {
        int r = tid >> 1, seg = tid & 1;
        int gr = rowBase + r;
        if (gr < N_NODES) {
            const float* cr = &C_f[r * LDC1 + seg * 64];
            __half* hp = g_H + (size_t)gr * HID + seg * 64;
#pragma unroll
            for (int q = 0; q < 8; q++) {
                float4 v0 = *(const float4*)(cr + q * 8);
                float4 v1 = *(const float4*)(cr + q * 8 + 4);
                uint4 o;
                o.x = h2u(v0.x, v0.y);
                o.y = h2u(v0.z, v0.w);
                o.z = h2u(v1.x, v1.y);
                o.w = h2u(v1.z, v1.w);
                *(uint4*)(hp + q * 8) = o;
            }
        }
    }
}

// ---------------- layer-1 aggregate (dinv[s] folded in) + relu + bias ---------
// warp per node; lane covers 4 consecutive cols (uint2 = 4 halfs)
__global__ void k_agg1(const float* __restrict__ b1) {
    int gw = (blockIdx.x * blockDim.x + threadIdx.x) >> 5;
    if (gw >= N_NODES) return;
    const int lane = threadIdx.x & 31;
    const uint2* hs = (const uint2*)g_H;      // row stride = 32 uint2

    float di = __ldg(&g_dinv[gw]);
    uint2 sv = __ldg(hs + (size_t)gw * 32 + lane);   // self loop: dinv[d]*H[d]
    float2 f0 = u2f(sv.x), f1 = u2f(sv.y);
    float4 acc = make_float4(di * f0.x, di * f0.y, di * f1.x, di * f1.y);

    int beg = __ldg(&g_rowptr[gw]);
    int end = beg + __ldg(&g_cnt[gw]);
    int i = beg;
    for (; i + 4 <= end; i += 4) {
        int s0 = __ldg(g_adj + i),     s1 = __ldg(g_adj + i + 1);
        int s2 = __ldg(g_adj + i + 2), s3 = __ldg(g_adj + i + 3);
        float w0 = __ldg(&g_dinv[s0]), w1 = __ldg(&g_dinv[s1]);
        float w2 = __ldg(&g_dinv[s2]), w3 = __ldg(&g_dinv[s3]);
        uint2 v0 = __ldg(hs + (size_t)s0 * 32 + lane);
        uint2 v1 = __ldg(hs + (size_t)s1 * 32 + lane);
        uint2 v2 = __ldg(hs + (size_t)s2 * 32 + lane);
        uint2 v3 = __ldg(hs + (size_t)s3 * 32 + lane);
        float2 a0 = u2f(v0.x), a1 = u2f(v0.y);
        float2 b0 = u2f(v1.x), b1v = u2f(v1.y);
        float2 c0 = u2f(v2.x), c1 = u2f(v2.y);
        float2 d0 = u2f(v3.x), d1 = u2f(v3.y);
        acc.x = fmaf(w0, a0.x, fmaf(w1, b0.x, fmaf(w2, c0.x, fmaf(w3, d0.x, acc.x))));
        acc.y = fmaf(w0, a0.y, fmaf(w1, b0.y, fmaf(w2, c0.y, fmaf(w3, d0.y, acc.y))));
        acc.z = fmaf(w0, a1.x, fmaf(w1, b1v.x, fmaf(w2, c1.x, fmaf(w3, d1.x, acc.z))));
        acc.w = fmaf(w0, a1.y, fmaf(w1, b1v.y, fmaf(w2, c1.y, fmaf(w3, d1.y, acc.w))));
    }
    for (; i < end; i++) {
        int s = __ldg(g_adj + i);
        float w = __ldg(&g_dinv[s]);
        uint2 v = __ldg(hs + (size_t)s * 32 + lane);
        float2 a0 = u2f(v.x), a1 = u2f(v.y);
        acc.x = fmaf(w, a0.x, acc.x);
        acc.y = fmaf(w, a0.y, acc.y);
        acc.z = fmaf(w, a1.x, acc.z);
        acc.w = fmaf(w, a1.y, acc.w);
    }
    float4 b = __ldg((const float4*)b1 + lane);
    float rx = fmaxf(fmaf(di, acc.x, b.x), 0.0f);
    float ry = fmaxf(fmaf(di, acc.y, b.y), 0.0f);
    float rz = fmaxf(fmaf(di, acc.z, b.z), 0.0f);
    float rw = fmaxf(fmaf(di, acc.w, b.w), 0.0f);
    uint2 o;
    o.x = h2u(rx, ry);
    o.y = h2u(rz, rw);
    ((uint2*)g_X1h)[(size_t)gw * 32 + lane] = o;
}

// ---------------- layer-2 GEMM (tensor cores): Hs2 = dinv * (x1 @ W2), fp16 out
#define LDA2 136
#define LDB2 72
#define LDC2 68
__global__ __launch_bounds__(256)
void k_gemm2_tc(const float* __restrict__ W2) {
    extern __shared__ char dynsmem[];
    __half* A_h = (__half*)dynsmem;                 // [128][136]
    __half* B_h = A_h + 128 * LDA2;                 // [128][72]
    float*  C_f = (float*)dynsmem;                  // [128][68] (reuse)

    const int tid  = threadIdx.x;
    const int warp = tid >> 5;
    const int rowBase = blockIdx.x * 128;

    // fill B: W2 fp32 -> fp16 (128x64)
    for (int idx = tid; idx < 128 * 32; idx += 256) {
        int k = idx >> 5, n2 = idx & 31;
        float2 w = *(const float2*)&W2[k * RPR + n2 * 2];
        *(unsigned int*)&B_h[k * LDB2 + n2 * 2] = h2u(w.x, w.y);
    }
    // fill A: X1h fp16 direct copy (uint4 = 8 halfs)
    for (int idx = tid; idx < 128 * 16; idx += 256) {
        int r = idx >> 4, q = idx & 15;
        int gr = rowBase + r;
        uint4 v = make_uint4(0, 0, 0, 0);
        if (gr < N_NODES)
            v = *(const uint4*)&g_X1h[(size_t)gr * HID + q * 8];
        *(uint4*)&A_h[r * LDA2 + q * 8] = v;
    }
    __syncthreads();

    wmma::fragment<wmma::accumulator, 16, 16, 16, float> acc[4];
#pragma unroll
    for (int n = 0; n < 4; n++) wmma::fill_fragment(acc[n], 0.0f);

#pragma unroll
    for (int k = 0; k < 8; k++) {
        wmma::fragment<wmma::matrix_a, 16, 16, 16, __half, wmma::row_major> a;
        wmma::load_matrix_sync(a, &A_h[warp * 16 * LDA2 + k * 16], LDA2);
#pragma unroll
        for (int n = 0; n < 4; n++) {
            wmma::fragment<wmma::matrix_b, 16, 16, 16, __half, wmma::row_major> b;
            wmma::load_matrix_sync(b, &B_h[k * 16 * LDB2 + n * 16], LDB2);
            wmma::mma_sync(acc[n], a, b, acc[n]);
        }
    }
    __syncthreads();

#pragma unroll
    for (int n = 0; n < 4; n++)
        wmma::store_matrix_sync(&C_f[warp * 16 * LDC2 + n * 16], acc[n], LDC2,
                                wmma::mem_row_major);
    __syncthreads();

    // epilogue: 2 threads/row, 32 cols each
    {
        int r = tid >> 1, seg = tid & 1;
        int gr = rowBase + r;
        if (gr < N_NODES) {
            float di = __ldg(&g_dinv[gr]);
            const float* cr = &C_f[r * LDC2 + seg * 32];
            __half* hp = g_Hs2 + (size_t)gr * RPR + seg * 32;
#pragma unroll
            for (int q = 0; q < 4; q++) {
                float4 v0 = *(const float4*)(cr + q * 8);
                float4 v1 = *(const float4*)(cr + q * 8 + 4);
                uint4 o;
                o.x = h2u(v0.x * di, v0.y * di);
                o.y = h2u(v0.z * di, v0.w * di);
                o.z = h2u(v1.x * di, v1.y * di);
                o.w = h2u(v1.z * di, v1.w * di);
                *(uint4*)(hp + q * 8) = o;
            }
        }
    }
}

// ---------------- layer-2 aggregate + bias -> out ----------------
// half-warp (16 lanes x uint2 = 64 halfs) per node
__global__ void k_agg2(const float* __restrict__ b2, float* __restrict__ out) {
    int gh = (blockIdx.x * blockDim.x + threadIdx.x) >> 4;
    if (gh >= N_NODES) return;
    const int l = threadIdx.x & 15;
    const uint2* hs = (const uint2*)g_Hs2;    // row stride = 16 uint2

    uint2 sv = __ldg(hs + (size_t)gh * 16 + l);   // self loop
    float2 f0 = u2f(sv.x), f1 = u2f(sv.y);
    float4 acc = make_float4(f0.x, f0.y, f1.x, f1.y);

    int beg = __ldg(&g_rowptr[gh]);
    int end = beg + __ldg(&g_cnt[gh]);
    int i = beg;
    for (; i + 4 <= end; i += 4) {
        int s0 = __ldg(g_adj + i),     s1 = __ldg(g_adj + i + 1);
        int s2 = __ldg(g_adj + i + 2), s3 = __ldg(g_adj + i + 3);
        uint2 v0 = __ldg(hs + (size_t)s0 * 16 + l);
        uint2 v1 = __ldg(hs + (size_t)s1 * 16 + l);
        uint2 v2 = __ldg(hs + (size_t)s2 * 16 + l);
        uint2 v3 = __ldg(hs + (size_t)s3 * 16 + l);
        float2 a0 = u2f(v0.x), a1 = u2f(v0.y);
        float2 b0 = u2f(v1.x), b1v = u2f(v1.y);
        float2 c0 = u2f(v2.x), c1 = u2f(v2.y);
        float2 d0 = u2f(v3.x), d1 = u2f(v3.y);
        acc.x += (a0.x + b0.x) + (c0.x + d0.x);
        acc.y += (a0.y + b0.y) + (c0.y + d0.y);
        acc.z += (a1.x + b1v.x) + (c1.x + d1.x);
        acc.w += (a1.y + b1v.y) + (c1.y + d1.y);
    }
    for (; i < end; i++) {
        int s = __ldg(g_adj + i);
        uint2 v = __ldg(hs + (size_t)s * 16 + l);
        float2 a0 = u2f(v.x), a1 = u2f(v.y);
        acc.x += a0.x; acc.y += a0.y; acc.z += a1.x; acc.w += a1.y;
    }
    float di = __ldg(&g_dinv[gh]);
    float4 b = __ldg((const float4*)b2 + l);
    ((float4*)out)[(size_t)gh * 16 + l] =
        make_float4(fmaf(di, acc.x, b.x), fmaf(di, acc.y, b.y),
                    fmaf(di, acc.z, b.z), fmaf(di, acc.w, b.w));
}

// ---------------- launch ----------------
#define SMEM_GEMM1 (2 * 128 * LDA1 * 2)                 // 69632 B
#define SMEM_GEMM2 (128 * LDA2 * 2 + 128 * LDB2 * 2)    // 53248 B

extern "C" void kernel_launch(void* const* d_in, const int* in_sizes, int n_in,
                              void* d_out, int out_size) {
    const int*   edge = (const int*)d_in[0];     // [2, E]: src row, dst row
    const float* x    = (const float*)d_in[1];   // [N, 128]
    const float* W1   = (const float*)d_in[2];   // [128, 128]
    const float* b1   = (const float*)d_in[3];   // [128]
    const float* W2   = (const float*)d_in[4];   // [128, 64]
    const float* b2   = (const float*)d_in[5];   // [64]
    float* out = (float*)d_out;                  // [N, 64]

    const int* src = edge;
    const int* dst = edge + N_EDGES;

    // lazily-created side stream + events (created on the first, uncaptured,
    // correctness call; reused identically on every call thereafter)
    static cudaStream_t s_side = nullptr;
    static cudaEvent_t  s_evFork = nullptr, s_evJoin = nullptr;
    if (s_side == nullptr) {
        cudaStreamCreateWithFlags(&s_side, cudaStreamNonBlocking);
        cudaEventCreateWithFlags(&s_evFork, cudaEventDisableTiming);
        cudaEventCreateWithFlags(&s_evJoin, cudaEventDisableTiming);
    }

    cudaFuncSetAttribute(k_gemm1_tc, cudaFuncAttributeMaxDynamicSharedMemorySize,
                         SMEM_GEMM1);
    cudaFuncSetAttribute(k_gemm2_tc, cudaFuncAttributeMaxDynamicSharedMemorySize,
                         SMEM_GEMM2);

    // fork at t=0: gemm1 (no dependencies) overlaps the entire CSR build
    cudaEventRecord(s_evFork, 0);
    cudaStreamWaitEvent(s_side, s_evFork, 0);
    k_gemm1_tc<<<(N_NODES + 127) / 128, 256, SMEM_GEMM1, s_side>>>(x, W1);
    cudaEventRecord(s_evJoin, s_side);

    // CSR build on main stream, concurrent with gemm1
    k_zero<<<SCAN_BLOCKS, 256>>>();
    k_hist<<<2048, 256>>>(dst);
    k_scan<<<SCAN_BLOCKS, 256>>>();
    k_fill<<<2048, 256>>>(src, dst);

    // join: agg1 needs adj (fill), dinv (scan) and H (gemm1)
    cudaStreamWaitEvent(0, s_evJoin, 0);

    k_agg1<<<(N_NODES * 32 + 255) / 256, 256>>>(b1);
    k_gemm2_tc<<<(N_NODES + 127) / 128, 256, SMEM_GEMM2>>>(W2);
    k_agg2<<<(N_NODES * 16 + 255) / 256, 256>>>(b2, out);
}

// round 14
// speedup vs baseline: 1.0218x; 1.0218x over previous
#include <cuda_runtime.h>
#include <cuda_fp16.h>
#include <mma.h>
#include <cstdint>

using namespace nvcuda;

// GCN: out = GCNConv2( relu(GCNConv1(x)) )
// Hs = dinv ⊙ (X W1) via fp16 tensor cores (fp32 accum), fp16 messages;
// agg1: x1 = relu(dinv*(Hs[d] + gather)+b1) (fp16);  gemm2: Hs2 = dinv*(x1 @ W2);
// agg2: out = dinv*(Hs2[d] + gather) + b2 (fp32).  All serial (overlap regressed).

#define N_NODES 100000
#define N_EDGES 1600000
#define EMB 128
#define HID 128
#define RPR 64
#define SCAN_BLOCKS 391   // ceil(100000/256)

// ---------------- scratch (device globals, allocation-free) ----------------
__device__ float  g_dinv[N_NODES];
__device__ __half g_Hs [(long long)N_NODES * HID];   // layer1 scaled hidden (fp16)
__device__ __half g_X1h[(long long)N_NODES * HID];   // relu(conv1) output (fp16)
__device__ __half g_Hs2[(long long)N_NODES * RPR];   // layer2 scaled hidden (fp16)
__device__ int    g_cnt[N_NODES];
__device__ int    g_rowptr[N_NODES];                  // start; end = start + cnt
__device__ int    g_cur[N_NODES];
__device__ int    g_total;
__device__ int    g_adj[N_EDGES];

// ---------------- helpers ----------------
__device__ __forceinline__ unsigned int h2u(float a, float b) {
    __half2 h = __floats2half2_rn(a, b);
    return *reinterpret_cast<unsigned int*>(&h);
}
__device__ __forceinline__ float2 u2f(unsigned int u) {
    __half2 h = *reinterpret_cast<__half2*>(&u);
    return __half22float2(h);
}

// ---------------- CSR build + degree ----------------
__global__ void k_zero() {
    int i = blockIdx.x * blockDim.x + threadIdx.x;
    if (i < N_NODES) g_cnt[i] = 0;
    if (i == 0) g_total = 0;
}

// 4 edges per iteration: 4 independent ATOMGs in flight per thread
__global__ void k_hist(const int* __restrict__ dst) {
    int stride = gridDim.x * blockDim.x;
    const int4* d4 = (const int4*)dst;
    for (int e = blockIdx.x * blockDim.x + threadIdx.x; e < N_EDGES / 4; e += stride) {
        int4 d = __ldg(d4 + e);
        atomicAdd(&g_cnt[d.x], 1);
        atomicAdd(&g_cnt[d.y], 1);
        atomicAdd(&g_cnt[d.z], 1);
        atomicAdd(&g_cnt[d.w], 1);
    }
}

// single-kernel scan: block prefix sum + atomic base (rowptr need not be
// globally monotonic; agg uses end = rowptr + cnt)
__global__ void k_scan() {
    __shared__ int sh[256];
    __shared__ int base;
    int t = threadIdx.x;
    int i = blockIdx.x * 256 + t;
    int v = (i < N_NODES) ? g_cnt[i] : 0;
    sh[t] = v;
    __syncthreads();
    for (int off = 1; off < 256; off <<= 1) {
        int add = 0;
        if (t >= off) add = sh[t - off];
        __syncthreads();
        sh[t] += add;
        __syncthreads();
    }
    if (t == 255) base = atomicAdd(&g_total, sh[255]);
    __syncthreads();
    int excl = base + sh[t] - v;
    if (i < N_NODES) {
        g_rowptr[i] = excl;
        g_cur[i]    = excl;
        g_dinv[i]   = rsqrtf(1.0f + (float)v);   // +1 for self loop
    }
}

// 4 edges per iteration
__global__ void k_fill(const int* __restrict__ src, const int* __restrict__ dst) {
    int stride = gridDim.x * blockDim.x;
    const int4* s4 = (const int4*)src;
    const int4* d4 = (const int4*)dst;
    for (int e = blockIdx.x * blockDim.x + threadIdx.x; e < N_EDGES / 4; e += stride) {
        int4 s = __ldg(s4 + e);
        int4 d = __ldg(d4 + e);
        int p0 = atomicAdd(&g_cur[d.x], 1);
        int p1 = atomicAdd(&g_cur[d.y], 1);
        int p2 = atomicAdd(&g_cur[d.z], 1);
        int p3 = atomicAdd(&g_cur[d.w], 1);
        g_adj[p0] = s.x;
        g_adj[p1] = s.y;
        g_adj[p2] = s.z;
        g_adj[p3] = s.w;
    }
}

// ---------------- layer-1 GEMM (tensor cores): Hs = dinv * (x @ W1), fp16 out ---
#define LDA1 136
#define LDC1 132
__global__ __launch_bounds__(256)
void k_gemm1_tc(const float* __restrict__ x, const float* __restrict__ W1) {
    extern __shared__ char dynsmem[];
    __half* A_h = (__half*)dynsmem;                 // [128][136]
    __half* B_h = A_h + 128 * LDA1;                 // [128][136]
    float*  C_f = (float*)dynsmem;                  // [128][132] (reuse after mma)

    const int tid  = threadIdx.x;
    const int warp = tid >> 5;
    const int rowBase = blockIdx.x * 128;

    // fill B: W1 fp32 -> fp16 (128x128), pairs
    for (int idx = tid; idx < 128 * 64; idx += 256) {
        int k = idx >> 6, n2 = idx & 63;
        float2 w = *(const float2*)&W1[k * HID + n2 * 2];
        *(unsigned int*)&B_h[k * LDA1 + n2 * 2] = h2u(w.x, w.y);
    }
    // fill A: x tile fp32 -> fp16, zero-pad invalid rows
    for (int idx = tid; idx < 128 * 32; idx += 256) {
        int r = idx >> 5, q4 = idx & 31;
        int gr = rowBase + r;
        unsigned int p0 = 0, p1 = 0;
        if (gr < N_NODES) {
            float4 v = *(const float4*)&x[(size_t)gr * EMB + q4 * 4];
            p0 = h2u(v.x, v.y);
            p1 = h2u(v.z, v.w);
        }
        *(unsigned int*)&A_h[r * LDA1 + q4 * 4]     = p0;
        *(unsigned int*)&A_h[r * LDA1 + q4 * 4 + 2] = p1;
    }
    __syncthreads();

    wmma::fragment<wmma::accumulator, 16, 16, 16, float> acc[8];
#pragma unroll
    for (int n = 0; n < 8; n++) wmma::fill_fragment(acc[n], 0.0f);

#pragma unroll
    for (int k = 0; k < 8; k++) {
        wmma::fragment<wmma::matrix_a, 16, 16, 16, __half, wmma::row_major> a;
        wmma::load_matrix_sync(a, &A_h[warp * 16 * LDA1 + k * 16], LDA1);
#pragma unroll
        for (int n = 0; n < 8; n++) {
            wmma::fragment<wmma::matrix_b, 16, 16, 16, __half, wmma::row_major> b;
            wmma::load_matrix_sync(b, &B_h[k * 16 * LDA1 + n * 16], LDA1);
            wmma::mma_sync(acc[n], a, b, acc[n]);
        }
    }
    __syncthreads();   // done reading A/B smem; reuse as C staging

#pragma unroll
    for (int n = 0; n < 8; n++)
        wmma::store_matrix_sync(&C_f[warp * 16 * LDC1 + n * 16], acc[n], LDC1,
                                wmma::mem_row_major);
    __syncthreads();

    // epilogue: scale by dinv, convert fp16, write. 2 threads/row, 64 cols each.
    {
        int r = tid >> 1, seg = tid & 1;
        int gr = rowBase + r;
        if (gr < N_NODES) {
            float di = __ldg(&g_dinv[gr]);
            const float* cr = &C_f[r * LDC1 + seg * 64];
            __half* hp = g_Hs + (size_t)gr * HID + seg * 64;
#pragma unroll
            for (int q = 0; q < 8; q++) {
                float4 v0 = *(const float4*)(cr + q * 8);
                float4 v1 = *(const float4*)(cr + q * 8 + 4);
                uint4 o;
                o.x = h2u(v0.x * di, v0.y * di);
                o.y = h2u(v0.z * di, v0.w * di);
                o.z = h2u(v1.x * di, v1.y * di);
                o.w = h2u(v1.z * di, v1.w * di);
                *(uint4*)(hp + q * 8) = o;
            }
        }
    }
}

// ---------------- layer-1 aggregate + relu + bias -> x1 (fp16) ----------------
// warp per node; lane covers 4 consecutive cols (uint2 = 4 halfs); 8-deep MLP
__global__ void k_agg1(const float* __restrict__ b1) {
    int gw = (blockIdx.x * blockDim.x + threadIdx.x) >> 5;
    if (gw >= N_NODES) return;
    const int lane = threadIdx.x & 31;
    const uint2* hs = (const uint2*)g_Hs;     // row stride = 32 uint2

    uint2 sv = __ldg(hs + (size_t)gw * 32 + lane);   // self loop
    float2 f0 = u2f(sv.x), f1 = u2f(sv.y);
    float4 acc = make_float4(f0.x, f0.y, f1.x, f1.y);

    int beg = __ldg(&g_rowptr[gw]);
    int end = beg + __ldg(&g_cnt[gw]);
    int i = beg;
    for (; i + 8 <= end; i += 8) {
        int s[8];
#pragma unroll
        for (int q = 0; q < 8; q++) s[q] = __ldg(g_adj + i + q);
        uint2 v[8];
#pragma unroll
        for (int q = 0; q < 8; q++) v[q] = __ldg(hs + (size_t)s[q] * 32 + lane);
#pragma unroll
        for (int q = 0; q < 8; q++) {
            float2 a0 = u2f(v[q].x), a1 = u2f(v[q].y);
            acc.x += a0.x; acc.y += a0.y; acc.z += a1.x; acc.w += a1.y;
        }
    }
    if (i + 4 <= end) {
        int s[4];
#pragma unroll
        for (int q = 0; q < 4; q++) s[q] = __ldg(g_adj + i + q);
        uint2 v[4];
#pragma unroll
        for (int q = 0; q < 4; q++) v[q] = __ldg(hs + (size_t)s[q] * 32 + lane);
#pragma unroll
        for (int q = 0; q < 4; q++) {
            float2 a0 = u2f(v[q].x), a1 = u2f(v[q].y);
            acc.x += a0.x; acc.y += a0.y; acc.z += a1.x; acc.w += a1.y;
        }
        i += 4;
    }
    for (; i < end; i++) {
        int s = __ldg(g_adj + i);
        uint2 v = __ldg(hs + (size_t)s * 32 + lane);
        float2 a0 = u2f(v.x), a1 = u2f(v.y);
        acc.x += a0.x; acc.y += a0.y; acc.z += a1.x; acc.w += a1.y;
    }
    float di = __ldg(&g_dinv[gw]);
    float4 b = __ldg((const float4*)b1 + lane);
    float rx = fmaxf(fmaf(di, acc.x, b.x), 0.0f);
    float ry = fmaxf(fmaf(di, acc.y, b.y), 0.0f);
    float rz = fmaxf(fmaf(di, acc.z, b.z), 0.0f);
    float rw = fmaxf(fmaf(di, acc.w, b.w), 0.0f);
    uint2 o;
    o.x = h2u(rx, ry);
    o.y = h2u(rz, rw);
    ((uint2*)g_X1h)[(size_t)gw * 32 + lane] = o;
}

// ---------------- layer-2 GEMM (tensor cores): Hs2 = dinv * (x1 @ W2), fp16 out
#define LDA2 136
#define LDB2 72
#define LDC2 68
__global__ __launch_bounds__(256)
void k_gemm2_tc(const float* __restrict__ W2) {
    extern __shared__ char dynsmem[];
    __half* A_h = (__half*)dynsmem;                 // [128][136]
    __half* B_h = A_h + 128 * LDA2;                 // [128][72]
    float*  C_f = (float*)dynsmem;                  // [128][68] (reuse)

    const int tid  = threadIdx.x;
    const int warp = tid >> 5;
    const int rowBase = blockIdx.x * 128;

    // fill B: W2 fp32 -> fp16 (128x64)
    for (int idx = tid; idx < 128 * 32; idx += 256) {
        int k = idx >> 5, n2 = idx & 31;
        float2 w = *(const float2*)&W2[k * RPR + n2 * 2];
        *(unsigned int*)&B_h[k * LDB2 + n2 * 2] = h2u(w.x, w.y);
    }
    // fill A: X1h fp16 direct copy (uint4 = 8 halfs)
    for (int idx = tid; idx < 128 * 16; idx += 256) {
        int r = idx >> 4, q = idx & 15;
        int gr = rowBase + r;
        uint4 v = make_uint4(0, 0, 0, 0);
        if (gr < N_NODES)
            v = *(const uint4*)&g_X1h[(size_t)gr * HID + q * 8];
        *(uint4*)&A_h[r * LDA2 + q * 8] = v;
    }
    __syncthreads();

    wmma::fragment<wmma::accumulator, 16, 16, 16, float> acc[4];
#pragma unroll
    for (int n = 0; n < 4; n++) wmma::fill_fragment(acc[n], 0.0f);

#pragma unroll
    for (int k = 0; k < 8; k++) {
        wmma::fragment<wmma::matrix_a, 16, 16, 16, __half, wmma::row_major> a;
        wmma::load_matrix_sync(a, &A_h[warp * 16 * LDA2 + k * 16], LDA2);
#pragma unroll
        for (int n = 0; n < 4; n++) {
            wmma::fragment<wmma::matrix_b, 16, 16, 16, __half, wmma::row_major> b;
            wmma::load_matrix_sync(b, &B_h[k * 16 * LDB2 + n * 16], LDB2);
            wmma::mma_sync(acc[n], a, b, acc[n]);
        }
    }
    __syncthreads();

#pragma unroll
    for (int n = 0; n < 4; n++)
        wmma::store_matrix_sync(&C_f[warp * 16 * LDC2 + n * 16], acc[n], LDC2,
                                wmma::mem_row_major);
    __syncthreads();

    // epilogue: 2 threads/row, 32 cols each
    {
        int r = tid >> 1, seg = tid & 1;
        int gr = rowBase + r;
        if (gr < N_NODES) {
            float di = __ldg(&g_dinv[gr]);
            const float* cr = &C_f[r * LDC2 + seg * 32];
            __half* hp = g_Hs2 + (size_t)gr * RPR + seg * 32;
#pragma unroll
            for (int q = 0; q < 4; q++) {
                float4 v0 = *(const float4*)(cr + q * 8);
                float4 v1 = *(const float4*)(cr + q * 8 + 4);
                uint4 o;
                o.x = h2u(v0.x * di, v0.y * di);
                o.y = h2u(v0.z * di, v0.w * di);
                o.z = h2u(v1.x * di, v1.y * di);
                o.w = h2u(v1.z * di, v1.w * di);
                *(uint4*)(hp + q * 8) = o;
            }
        }
    }
}

// ---------------- layer-2 aggregate + bias -> out ----------------
// half-warp (16 lanes x uint2 = 64 halfs) per node; 8-deep MLP
__global__ void k_agg2(const float* __restrict__ b2, float* __restrict__ out) {
    int gh = (blockIdx.x * blockDim.x + threadIdx.x) >> 4;
    if (gh >= N_NODES) return;
    const int l = threadIdx.x & 15;
    const uint2* hs = (const uint2*)g_Hs2;    // row stride = 16 uint2

    uint2 sv = __ldg(hs + (size_t)gh * 16 + l);   // self loop
    float2 f0 = u2f(sv.x), f1 = u2f(sv.y);
    float4 acc = make_float4(f0.x, f0.y, f1.x, f1.y);

    int beg = __ldg(&g_rowptr[gh]);
    int end = beg + __ldg(&g_cnt[gh]);
    int i = beg;
    for (; i + 8 <= end; i += 8) {
        int s[8];
#pragma unroll
        for (int q = 0; q < 8; q++) s[q] = __ldg(g_adj + i + q);
        uint2 v[8];
#pragma unroll
        for (int q = 0; q < 8; q++) v[q] = __ldg(hs + (size_t)s[q] * 16 + l);
#pragma unroll
        for (int q = 0; q < 8; q++) {
            float2 a0 = u2f(v[q].x), a1 = u2f(v[q].y);
            acc.x += a0.x; acc.y += a0.y; acc.z += a1.x; acc.w += a1.y;
        }
    }
    if (i + 4 <= end) {
        int s[4];
#pragma unroll
        for (int q = 0; q < 4; q++) s[q] = __ldg(g_adj + i + q);
        uint2 v[4];
#pragma unroll
        for (int q = 0; q < 4; q++) v[q] = __ldg(hs + (size_t)s[q] * 16 + l);
#pragma unroll
        for (int q = 0; q < 4; q++) {
            float2 a0 = u2f(v[q].x), a1 = u2f(v[q].y);
            acc.x += a0.x; acc.y += a0.y; acc.z += a1.x; acc.w += a1.y;
        }
        i += 4;
    }
    for (; i < end; i++) {
        int s = __ldg(g_adj + i);
        uint2 v = __ldg(hs + (size_t)s * 16 + l);
        float2 a0 = u2f(v.x), a1 = u2f(v.y);
        acc.x += a0.x; acc.y += a0.y; acc.z += a1.x; acc.w += a1.y;
    }
    float di = __ldg(&g_dinv[gh]);
    float4 b = __ldg((const float4*)b2 + l);
    ((float4*)out)[(size_t)gh * 16 + l] =
        make_float4(fmaf(di, acc.x, b.x), fmaf(di, acc.y, b.y),
                    fmaf(di, acc.z, b.z), fmaf(di, acc.w, b.w));
}

// ---------------- launch ----------------
#define SMEM_GEMM1 (2 * 128 * LDA1 * 2)                 // 69632 B
#define SMEM_GEMM2 (128 * LDA2 * 2 + 128 * LDB2 * 2)    // 53248 B

extern "C" void kernel_launch(void* const* d_in, const int* in_sizes, int n_in,
                              void* d_out, int out_size) {
    const int*   edge = (const int*)d_in[0];     // [2, E]: src row, dst row
    const float* x    = (const float*)d_in[1];   // [N, 128]
    const float* W1   = (const float*)d_in[2];   // [128, 128]
    const float* b1   = (const float*)d_in[3];   // [128]
    const float* W2   = (const float*)d_in[4];   // [128, 64]
    const float* b2   = (const float*)d_in[5];   // [64]
    float* out = (float*)d_out;                  // [N, 64]

    const int* src = edge;
    const int* dst = edge + N_EDGES;

    cudaFuncSetAttribute(k_gemm1_tc, cudaFuncAttributeMaxDynamicSharedMemorySize,
                         SMEM_GEMM1);
    cudaFuncSetAttribute(k_gemm2_tc, cudaFuncAttributeMaxDynamicSharedMemorySize,
                         SMEM_GEMM2);

    // CSR build (+ degree/dinv)
    k_zero<<<SCAN_BLOCKS, 256>>>();
    k_hist<<<2048, 256>>>(dst);
    k_scan<<<SCAN_BLOCKS, 256>>>();
    k_fill<<<2048, 256>>>(src, dst);

    // layer 1
    k_gemm1_tc<<<(N_NODES + 127) / 128, 256, SMEM_GEMM1>>>(x, W1);
    k_agg1<<<(N_NODES * 32 + 255) / 256, 256>>>(b1);

    // layer 2
    k_gemm2_tc<<<(N_NODES + 127) / 128, 256, SMEM_GEMM2>>>(W2);
    k_agg2<<<(N_NODES * 16 + 255) / 256, 256>>>(b2, out);
}

// round 15
// speedup vs baseline: 1.0334x; 1.0113x over previous
#include <cuda_runtime.h>
#include <cuda_fp16.h>
#include <mma.h>
#include <cstdint>

using namespace nvcuda;

// GCN: out = GCNConv2( relu(GCNConv1(x)) )
// Hs = dinv ⊙ (X W1) via fp16 tensor cores (fp32 accum), fp16 messages;
// agg1: x1 = relu(dinv*(Hs[d] + gather)+b1) (fp16);  gemm2: Hs2 = dinv*(x1 @ W2);
// agg2: out = dinv*(Hs2[d] + gather) + b2 (fp32).
// CSR build: hist captures per-edge rank (atomicAdd return), fill is atomic-free.

#define N_NODES 100000
#define N_EDGES 1600000
#define EMB 128
#define HID 128
#define RPR 64
#define SCAN_BLOCKS 391   // ceil(100000/256)

// ---------------- scratch (device globals, allocation-free) ----------------
__device__ float  g_dinv[N_NODES];
__device__ __half g_Hs [(long long)N_NODES * HID];   // layer1 scaled hidden (fp16)
__device__ __half g_X1h[(long long)N_NODES * HID];   // relu(conv1) output (fp16)
__device__ __half g_Hs2[(long long)N_NODES * RPR];   // layer2 scaled hidden (fp16)
__device__ int    g_cnt[N_NODES];
__device__ int    g_rowptr[N_NODES];                  // start; end = start + cnt
__device__ int    g_rank[N_EDGES];                    // per-edge rank within dst bucket
__device__ int    g_total;
__device__ int    g_adj[N_EDGES];

// ---------------- helpers ----------------
__device__ __forceinline__ unsigned int h2u(float a, float b) {
    __half2 h = __floats2half2_rn(a, b);
    return *reinterpret_cast<unsigned int*>(&h);
}
__device__ __forceinline__ float2 u2f(unsigned int u) {
    __half2 h = *reinterpret_cast<__half2*>(&u);
    return __half22float2(h);
}

// ---------------- CSR build + degree ----------------
__global__ void k_zero() {
    int i = blockIdx.x * blockDim.x + threadIdx.x;
    if (i < N_NODES) g_cnt[i] = 0;
    if (i == 0) g_total = 0;
}

// histogram + capture per-edge rank (the atomicAdd return value)
__global__ void k_hist(const int* __restrict__ dst) {
    int stride = gridDim.x * blockDim.x;
    const int4* d4 = (const int4*)dst;
    int4* r4 = (int4*)g_rank;
    for (int e = blockIdx.x * blockDim.x + threadIdx.x; e < N_EDGES / 4; e += stride) {
        int4 d = __ldg(d4 + e);
        int4 r;
        r.x = atomicAdd(&g_cnt[d.x], 1);
        r.y = atomicAdd(&g_cnt[d.y], 1);
        r.z = atomicAdd(&g_cnt[d.z], 1);
        r.w = atomicAdd(&g_cnt[d.w], 1);
        r4[e] = r;
    }
}

// single-kernel scan: block prefix sum + atomic base (rowptr need not be
// globally monotonic; agg uses end = rowptr + cnt)
__global__ void k_scan() {
    __shared__ int sh[256];
    __shared__ int base;
    int t = threadIdx.x;
    int i = blockIdx.x * 256 + t;
    int v = (i < N_NODES) ? g_cnt[i] : 0;
    sh[t] = v;
    __syncthreads();
    for (int off = 1; off < 256; off <<= 1) {
        int add = 0;
        if (t >= off) add = sh[t - off];
        __syncthreads();
        sh[t] += add;
        __syncthreads();
    }
    if (t == 255) base = atomicAdd(&g_total, sh[255]);
    __syncthreads();
    int excl = base + sh[t] - v;
    if (i < N_NODES) {
        g_rowptr[i] = excl;
        g_dinv[i]   = rsqrtf(1.0f + (float)v);   // +1 for self loop
    }
}

// atomic-free fill: slot = rowptr[dst] + rank (each slot written exactly once)
__global__ void k_fill(const int* __restrict__ src, const int* __restrict__ dst) {
    int stride = gridDim.x * blockDim.x;
    const int4* s4 = (const int4*)src;
    const int4* d4 = (const int4*)dst;
    const int4* r4 = (const int4*)g_rank;
    for (int e = blockIdx.x * blockDim.x + threadIdx.x; e < N_EDGES / 4; e += stride) {
        int4 s = __ldg(s4 + e);
        int4 d = __ldg(d4 + e);
        int4 r = __ldg(r4 + e);
        g_adj[__ldg(&g_rowptr[d.x]) + r.x] = s.x;
        g_adj[__ldg(&g_rowptr[d.y]) + r.y] = s.y;
        g_adj[__ldg(&g_rowptr[d.z]) + r.z] = s.z;
        g_adj[__ldg(&g_rowptr[d.w]) + r.w] = s.w;
    }
}

// ---------------- layer-1 GEMM (tensor cores): Hs = dinv * (x @ W1), fp16 out ---
#define LDA1 136
#define LDC1 132
__global__ __launch_bounds__(256)
void k_gemm1_tc(const float* __restrict__ x, const float* __restrict__ W1) {
    extern __shared__ char dynsmem[];
    __half* A_h = (__half*)dynsmem;                 // [128][136]
    __half* B_h = A_h + 128 * LDA1;                 // [128][136]
    float*  C_f = (float*)dynsmem;                  // [128][132] (reuse after mma)

    const int tid  = threadIdx.x;
    const int warp = tid >> 5;
    const int rowBase = blockIdx.x * 128;

    // fill B: W1 fp32 -> fp16 (128x128), pairs
    for (int idx = tid; idx < 128 * 64; idx += 256) {
        int k = idx >> 6, n2 = idx & 63;
        float2 w = *(const float2*)&W1[k * HID + n2 * 2];
        *(unsigned int*)&B_h[k * LDA1 + n2 * 2] = h2u(w.x, w.y);
    }
    // fill A: x tile fp32 -> fp16, zero-pad invalid rows
    for (int idx = tid; idx < 128 * 32; idx += 256) {
        int r = idx >> 5, q4 = idx & 31;
        int gr = rowBase + r;
        unsigned int p0 = 0, p1 = 0;
        if (gr < N_NODES) {
            float4 v = *(const float4*)&x[(size_t)gr * EMB + q4 * 4];
            p0 = h2u(v.x, v.y);
            p1 = h2u(v.z, v.w);
        }
        *(unsigned int*)&A_h[r * LDA1 + q4 * 4]     = p0;
        *(unsigned int*)&A_h[r * LDA1 + q4 * 4 + 2] = p1;
    }
    __syncthreads();

    wmma::fragment<wmma::accumulator, 16, 16, 16, float> acc[8];
#pragma unroll
    for (int n = 0; n < 8; n++) wmma::fill_fragment(acc[n], 0.0f);

#pragma unroll
    for (int k = 0; k < 8; k++) {
        wmma::fragment<wmma::matrix_a, 16, 16, 16, __half, wmma::row_major> a;
        wmma::load_matrix_sync(a, &A_h[warp * 16 * LDA1 + k * 16], LDA1);
#pragma unroll
        for (int n = 0; n < 8; n++) {
            wmma::fragment<wmma::matrix_b, 16, 16, 16, __half, wmma::row_major> b;
            wmma::load_matrix_sync(b, &B_h[k * 16 * LDA1 + n * 16], LDA1);
            wmma::mma_sync(acc[n], a, b, acc[n]);
        }
    }
    __syncthreads();   // done reading A/B smem; reuse as C staging

#pragma unroll
    for (int n = 0; n < 8; n++)
        wmma::store_matrix_sync(&C_f[warp * 16 * LDC1 + n * 16], acc[n], LDC1,
                                wmma::mem_row_major);
    __syncthreads();

    // epilogue: scale by dinv, convert fp16, write. 2 threads/row, 64 cols each.
    {
        int r = tid >> 1, seg = tid & 1;
        int gr = rowBase + r;
        if (gr < N_NODES) {
            float di = __ldg(&g_dinv[gr]);
            const float* cr = &C_f[r * LDC1 + seg * 64];
            __half* hp = g_Hs + (size_t)gr * HID + seg * 64;
#pragma unroll
            for (int q = 0; q < 8; q++) {
                float4 v0 = *(const float4*)(cr + q * 8);
                float4 v1 = *(const float4*)(cr + q * 8 + 4);
                uint4 o;
                o.x = h2u(v0.x * di, v0.y * di);
                o.y = h2u(v0.z * di, v0.w * di);
                o.z = h2u(v1.x * di, v1.y * di);
                o.w = h2u(v1.z * di, v1.w * di);
                *(uint4*)(hp + q * 8) = o;
            }
        }
    }
}

// ---------------- layer-1 aggregate + relu + bias -> x1 (fp16) ----------------
// warp per node; lane covers 4 consecutive cols (uint2 = 4 halfs)
__global__ void k_agg1(const float* __restrict__ b1) {
    int gw = (blockIdx.x * blockDim.x + threadIdx.x) >> 5;
    if (gw >= N_NODES) return;
    const int lane = threadIdx.x & 31;
    const uint2* hs = (const uint2*)g_Hs;     // row stride = 32 uint2

    uint2 sv = __ldg(hs + (size_t)gw * 32 + lane);   // self loop
    float2 f0 = u2f(sv.x), f1 = u2f(sv.y);
    float4 acc = make_float4(f0.x, f0.y, f1.x, f1.y);

    int beg = __ldg(&g_rowptr[gw]);
    int end = beg + __ldg(&g_cnt[gw]);
    int i = beg;
    for (; i + 4 <= end; i += 4) {
        int s0 = __ldg(g_adj + i),     s1 = __ldg(g_adj + i + 1);
        int s2 = __ldg(g_adj + i + 2), s3 = __ldg(g_adj + i + 3);
        uint2 v0 = __ldg(hs + (size_t)s0 * 32 + lane);
        uint2 v1 = __ldg(hs + (size_t)s1 * 32 + lane);
        uint2 v2 = __ldg(hs + (size_t)s2 * 32 + lane);
        uint2 v3 = __ldg(hs + (size_t)s3 * 32 + lane);
        float2 a0 = u2f(v0.x), a1 = u2f(v0.y);
        float2 b0 = u2f(v1.x), b1v = u2f(v1.y);
        float2 c0 = u2f(v2.x), c1 = u2f(v2.y);
        float2 d0 = u2f(v3.x), d1 = u2f(v3.y);
        acc.x += (a0.x + b0.x) + (c0.x + d0.x);
        acc.y += (a0.y + b0.y) + (c0.y + d0.y);
        acc.z += (a1.x + b1v.x) + (c1.x + d1.x);
        acc.w += (a1.y + b1v.y) + (c1.y + d1.y);
    }
    for (; i < end; i++) {
        int s = __ldg(g_adj + i);
        uint2 v = __ldg(hs + (size_t)s * 32 + lane);
        float2 a0 = u2f(v.x), a1 = u2f(v.y);
        acc.x += a0.x; acc.y += a0.y; acc.z += a1.x; acc.w += a1.y;
    }
    float di = __ldg(&g_dinv[gw]);
    float4 b = __ldg((const float4*)b1 + lane);
    float rx = fmaxf(fmaf(di, acc.x, b.x), 0.0f);
    float ry = fmaxf(fmaf(di, acc.y, b.y), 0.0f);
    float rz = fmaxf(fmaf(di, acc.z, b.z), 0.0f);
    float rw = fmaxf(fmaf(di, acc.w, b.w), 0.0f);
    uint2 o;
    o.x = h2u(rx, ry);
    o.y = h2u(rz, rw);
    ((uint2*)g_X1h)[(size_t)gw * 32 + lane] = o;
}

// ---------------- layer-2 GEMM (tensor cores): Hs2 = dinv * (x1 @ W2), fp16 out
#define LDA2 136
#define LDB2 72
#define LDC2 68
__global__ __launch_bounds__(256)
void k_gemm2_tc(const float* __restrict__ W2) {
    extern __shared__ char dynsmem[];
    __half* A_h = (__half*)dynsmem;                 // [128][136]
    __half* B_h = A_h + 128 * LDA2;                 // [128][72]
    float*  C_f = (float*)dynsmem;                  // [128][68] (reuse)

    const int tid  = threadIdx.x;
    const int warp = tid >> 5;
    const int rowBase = blockIdx.x * 128;

    // fill B: W2 fp32 -> fp16 (128x64)
    for (int idx = tid; idx < 128 * 32; idx += 256) {
        int k = idx >> 5, n2 = idx & 31;
        float2 w = *(const float2*)&W2[k * RPR + n2 * 2];
        *(unsigned int*)&B_h[k * LDB2 + n2 * 2] = h2u(w.x, w.y);
    }
    // fill A: X1h fp16 direct copy (uint4 = 8 halfs)
    for (int idx = tid; idx < 128 * 16; idx += 256) {
        int r = idx >> 4, q = idx & 15;
        int gr = rowBase + r;
        uint4 v = make_uint4(0, 0, 0, 0);
        if (gr < N_NODES)
            v = *(const uint4*)&g_X1h[(size_t)gr * HID + q * 8];
        *(uint4*)&A_h[r * LDA2 + q * 8] = v;
    }
    __syncthreads();

    wmma::fragment<wmma::accumulator, 16, 16, 16, float> acc[4];
#pragma unroll
    for (int n = 0; n < 4; n++) wmma::fill_fragment(acc[n], 0.0f);

#pragma unroll
    for (int k = 0; k < 8; k++) {
        wmma::fragment<wmma::matrix_a, 16, 16, 16, __half, wmma::row_major> a;
        wmma::load_matrix_sync(a, &A_h[warp * 16 * LDA2 + k * 16], LDA2);
#pragma unroll
        for (int n = 0; n < 4; n++) {
            wmma::fragment<wmma::matrix_b, 16, 16, 16, __half, wmma::row_major> b;
            wmma::load_matrix_sync(b, &B_h[k * 16 * LDB2 + n * 16], LDB2);
            wmma::mma_sync(acc[n], a, b, acc[n]);
        }
    }
    __syncthreads();

#pragma unroll
    for (int n = 0; n < 4; n++)
        wmma::store_matrix_sync(&C_f[warp * 16 * LDC2 + n * 16], acc[n], LDC2,
                                wmma::mem_row_major);
    __syncthreads();

    // epilogue: 2 threads/row, 32 cols each
    {
        int r = tid >> 1, seg = tid & 1;
        int gr = rowBase + r;
        if (gr < N_NODES) {
            float di = __ldg(&g_dinv[gr]);
            const float* cr = &C_f[r * LDC2 + seg * 32];
            __half* hp = g_Hs2 + (size_t)gr * RPR + seg * 32;
#pragma unroll
            for (int q = 0; q < 4; q++) {
                float4 v0 = *(const float4*)(cr + q * 8);
                float4 v1 = *(const float4*)(cr + q * 8 + 4);
                uint4 o;
                o.x = h2u(v0.x * di, v0.y * di);
                o.y = h2u(v0.z * di, v0.w * di);
                o.z = h2u(v1.x * di, v1.y * di);
                o.w = h2u(v1.z * di, v1.w * di);
                *(uint4*)(hp + q * 8) = o;
            }
        }
    }
}

// ---------------- layer-2 aggregate + bias -> out ----------------
// half-warp (16 lanes x uint2 = 64 halfs) per node
__global__ void k_agg2(const float* __restrict__ b2, float* __restrict__ out) {
    int gh = (blockIdx.x * blockDim.x + threadIdx.x) >> 4;
    if (gh >= N_NODES) return;
    const int l = threadIdx.x & 15;
    const uint2* hs = (const uint2*)g_Hs2;    // row stride = 16 uint2

    uint2 sv = __ldg(hs + (size_t)gh * 16 + l);   // self loop
    float2 f0 = u2f(sv.x), f1 = u2f(sv.y);
    float4 acc = make_float4(f0.x, f0.y, f1.x, f1.y);

    int beg = __ldg(&g_rowptr[gh]);
    int end = beg + __ldg(&g_cnt[gh]);
    int i = beg;
    for (; i + 4 <= end; i += 4) {
        int s0 = __ldg(g_adj + i),     s1 = __ldg(g_adj + i + 1);
        int s2 = __ldg(g_adj + i + 2), s3 = __ldg(g_adj + i + 3);
        uint2 v0 = __ldg(hs + (size_t)s0 * 16 + l);
        uint2 v1 = __ldg(hs + (size_t)s1 * 16 + l);
        uint2 v2 = __ldg(hs + (size_t)s2 * 16 + l);
        uint2 v3 = __ldg(hs + (size_t)s3 * 16 + l);
        float2 a0 = u2f(v0.x), a1 = u2f(v0.y);
        float2 b0 = u2f(v1.x), b1v = u2f(v1.y);
        float2 c0 = u2f(v2.x), c1 = u2f(v2.y);
        float2 d0 = u2f(v3.x), d1 = u2f(v3.y);
        acc.x += (a0.x + b0.x) + (c0.x + d0.x);
        acc.y += (a0.y + b0.y) + (c0.y + d0.y);
        acc.z += (a1.x + b1v.x) + (c1.x + d1.x);
        acc.w += (a1.y + b1v.y) + (c1.y + d1.y);
    }
    for (; i < end; i++) {
        int s = __ldg(g_adj + i);
        uint2 v = __ldg(hs + (size_t)s * 16 + l);
        float2 a0 = u2f(v.x), a1 = u2f(v.y);
        acc.x += a0.x; acc.y += a0.y; acc.z += a1.x; acc.w += a1.y;
    }
    float di = __ldg(&g_dinv[gh]);
    float4 b = __ldg((const float4*)b2 + l);
    ((float4*)out)[(size_t)gh * 16 + l] =
        make_float4(fmaf(di, acc.x, b.x), fmaf(di, acc.y, b.y),
                    fmaf(di, acc.z, b.z), fmaf(di, acc.w, b.w));
}

// ---------------- launch ----------------
#define SMEM_GEMM1 (2 * 128 * LDA1 * 2)                 // 69632 B
#define SMEM_GEMM2 (128 * LDA2 * 2 + 128 * LDB2 * 2)    // 53248 B

extern "C" void kernel_launch(void* const* d_in, const int* in_sizes, int n_in,
                              void* d_out, int out_size) {
    const int*   edge = (const int*)d_in[0];     // [2, E]: src row, dst row
    const float* x    = (const float*)d_in[1];   // [N, 128]
    const float* W1   = (const float*)d_in[2];   // [128, 128]
    const float* b1   = (const float*)d_in[3];   // [128]
    const float* W2   = (const float*)d_in[4];   // [128, 64]
    const float* b2   = (const float*)d_in[5];   // [64]
    float* out = (float*)d_out;                  // [N, 64]

    const int* src = edge;
    const int* dst = edge + N_EDGES;

    cudaFuncSetAttribute(k_gemm1_tc, cudaFuncAttributeMaxDynamicSharedMemorySize,
                         SMEM_GEMM1);
    cudaFuncSetAttribute(k_gemm2_tc, cudaFuncAttributeMaxDynamicSharedMemorySize,
                         SMEM_GEMM2);

    // CSR build (+ degree/dinv); fill is atomic-free (rank captured in hist)
    k_zero<<<SCAN_BLOCKS, 256>>>();
    k_hist<<<2048, 256>>>(dst);
    k_scan<<<SCAN_BLOCKS, 256>>>();
    k_fill<<<2048, 256>>>(src, dst);

    // layer 1
    k_gemm1_tc<<<(N_NODES + 127) / 128, 256, SMEM_GEMM1>>>(x, W1);
    k_agg1<<<(N_NODES * 32 + 255) / 256, 256>>>(b1);

    // layer 2
    k_gemm2_tc<<<(N_NODES + 127) / 128, 256, SMEM_GEMM2>>>(W2);
    k_agg2<<<(N_NODES * 16 + 255) / 256, 256>>>(b2, out);
}

// round 16
// speedup vs baseline: 1.0918x; 1.0565x over previous
#include <cuda_runtime.h>
#include <cuda_fp16.h>
#include <mma.h>
#include <cstdint>

using namespace nvcuda;

// GCN: out = GCNConv2( relu(GCNConv1(x)) )
// Hs = dinv ⊙ (X W1) via fp16 tensor cores (fp32 accum), fp16 messages;
// agg1: x1 = relu(dinv*(Hs[d] + gather)+b1) (fp16), half-warp/node, LDG.128;
// gemm2: Hs2 = dinv*(x1 @ W2);  agg2: out = dinv*(Hs2[d]+gather)+b2, 8-lane/node.
// CSR build: hist captures per-edge rank (atomicAdd return), fill is atomic-free.

#define N_NODES 100000
#define N_EDGES 1600000
#define EMB 128
#define HID 128
#define RPR 64
#define SCAN_BLOCKS 391   // ceil(100000/256)

// ---------------- scratch (device globals, allocation-free) ----------------
__device__ float  g_dinv[N_NODES];
__device__ __half g_Hs [(long long)N_NODES * HID];   // layer1 scaled hidden (fp16)
__device__ __half g_X1h[(long long)N_NODES * HID];   // relu(conv1) output (fp16)
__device__ __half g_Hs2[(long long)N_NODES * RPR];   // layer2 scaled hidden (fp16)
__device__ int    g_cnt[N_NODES];
__device__ int    g_rowptr[N_NODES];                  // start; end = start + cnt
__device__ int    g_rank[N_EDGES];                    // per-edge rank within dst bucket
__device__ int    g_total;
__device__ int    g_adj[N_EDGES];

// ---------------- helpers ----------------
__device__ __forceinline__ unsigned int h2u(float a, float b) {
    __half2 h = __floats2half2_rn(a, b);
    return *reinterpret_cast<unsigned int*>(&h);
}
__device__ __forceinline__ float2 u2f(unsigned int u) {
    __half2 h = *reinterpret_cast<__half2*>(&u);
    return __half22float2(h);
}
// accumulate 8 halfs (uint4) into 8 fp32 accumulators
__device__ __forceinline__ void acc8(float* a, uint4 v) {
    float2 p0 = u2f(v.x), p1 = u2f(v.y), p2 = u2f(v.z), p3 = u2f(v.w);
    a[0] += p0.x; a[1] += p0.y; a[2] += p1.x; a[3] += p1.y;
    a[4] += p2.x; a[5] += p2.y; a[6] += p3.x; a[7] += p3.y;
}

// ---------------- CSR build + degree ----------------
__global__ void k_zero() {
    int i = blockIdx.x * blockDim.x + threadIdx.x;
    if (i < N_NODES) g_cnt[i] = 0;
    if (i == 0) g_total = 0;
}

// histogram + capture per-edge rank (the atomicAdd return value)
__global__ void k_hist(const int* __restrict__ dst) {
    int stride = gridDim.x * blockDim.x;
    const int4* d4 = (const int4*)dst;
    int4* r4 = (int4*)g_rank;
    for (int e = blockIdx.x * blockDim.x + threadIdx.x; e < N_EDGES / 4; e += stride) {
        int4 d = __ldg(d4 + e);
        int4 r;
        r.x = atomicAdd(&g_cnt[d.x], 1);
        r.y = atomicAdd(&g_cnt[d.y], 1);
        r.z = atomicAdd(&g_cnt[d.z], 1);
        r.w = atomicAdd(&g_cnt[d.w], 1);
        r4[e] = r;
    }
}

// single-kernel scan: block prefix sum + atomic base (rowptr need not be
// globally monotonic; agg uses end = rowptr + cnt)
__global__ void k_scan() {
    __shared__ int sh[256];
    __shared__ int base;
    int t = threadIdx.x;
    int i = blockIdx.x * 256 + t;
    int v = (i < N_NODES) ? g_cnt[i] : 0;
    sh[t] = v;
    __syncthreads();
    for (int off = 1; off < 256; off <<= 1) {
        int add = 0;
        if (t >= off) add = sh[t - off];
        __syncthreads();
        sh[t] += add;
        __syncthreads();
    }
    if (t == 255) base = atomicAdd(&g_total, sh[255]);
    __syncthreads();
    int excl = base + sh[t] - v;
    if (i < N_NODES) {
        g_rowptr[i] = excl;
        g_dinv[i]   = rsqrtf(1.0f + (float)v);   // +1 for self loop
    }
}

// atomic-free fill: slot = rowptr[dst] + rank (each slot written exactly once)
__global__ void k_fill(const int* __restrict__ src, const int* __restrict__ dst) {
    int stride = gridDim.x * blockDim.x;
    const int4* s4 = (const int4*)src;
    const int4* d4 = (const int4*)dst;
    const int4* r4 = (const int4*)g_rank;
    for (int e = blockIdx.x * blockDim.x + threadIdx.x; e < N_EDGES / 4; e += stride) {
        int4 s = __ldg(s4 + e);
        int4 d = __ldg(d4 + e);
        int4 r = __ldg(r4 + e);
        g_adj[__ldg(&g_rowptr[d.x]) + r.x] = s.x;
        g_adj[__ldg(&g_rowptr[d.y]) + r.y] = s.y;
        g_adj[__ldg(&g_rowptr[d.z]) + r.z] = s.z;
        g_adj[__ldg(&g_rowptr[d.w]) + r.w] = s.w;
    }
}

// ---------------- layer-1 GEMM (tensor cores): Hs = dinv * (x @ W1), fp16 out ---
#define LDA1 136
#define LDC1 132
__global__ __launch_bounds__(256)
void k_gemm1_tc(const float* __restrict__ x, const float* __restrict__ W1) {
    extern __shared__ char dynsmem[];
    __half* A_h = (__half*)dynsmem;                 // [128][136]
    __half* B_h = A_h + 128 * LDA1;                 // [128][136]
    float*  C_f = (float*)dynsmem;                  // [128][132] (reuse after mma)

    const int tid  = threadIdx.x;
    const int warp = tid >> 5;
    const int rowBase = blockIdx.x * 128;

    // fill B: W1 fp32 -> fp16 (128x128), pairs
    for (int idx = tid; idx < 128 * 64; idx += 256) {
        int k = idx >> 6, n2 = idx & 63;
        float2 w = *(const float2*)&W1[k * HID + n2 * 2];
        *(unsigned int*)&B_h[k * LDA1 + n2 * 2] = h2u(w.x, w.y);
    }
    // fill A: x tile fp32 -> fp16, zero-pad invalid rows
    for (int idx = tid; idx < 128 * 32; idx += 256) {
        int r = idx >> 5, q4 = idx & 31;
        int gr = rowBase + r;
        unsigned int p0 = 0, p1 = 0;
        if (gr < N_NODES) {
            float4 v = *(const float4*)&x[(size_t)gr * EMB + q4 * 4];
            p0 = h2u(v.x, v.y);
            p1 = h2u(v.z, v.w);
        }
        *(unsigned int*)&A_h[r * LDA1 + q4 * 4]     = p0;
        *(unsigned int*)&A_h[r * LDA1 + q4 * 4 + 2] = p1;
    }
    __syncthreads();

    wmma::fragment<wmma::accumulator, 16, 16, 16, float> acc[8];
#pragma unroll
    for (int n = 0; n < 8; n++) wmma::fill_fragment(acc[n], 0.0f);

#pragma unroll
    for (int k = 0; k < 8; k++) {
        wmma::fragment<wmma::matrix_a, 16, 16, 16, __half, wmma::row_major> a;
        wmma::load_matrix_sync(a, &A_h[warp * 16 * LDA1 + k * 16], LDA1);
#pragma unroll
        for (int n = 0; n < 8; n++) {
            wmma::fragment<wmma::matrix_b, 16, 16, 16, __half, wmma::row_major> b;
            wmma::load_matrix_sync(b, &B_h[k * 16 * LDA1 + n * 16], LDA1);
            wmma::mma_sync(acc[n], a, b, acc[n]);
        }
    }
    __syncthreads();   // done reading A/B smem; reuse as C staging

#pragma unroll
    for (int n = 0; n < 8; n++)
        wmma::store_matrix_sync(&C_f[warp * 16 * LDC1 + n * 16], acc[n], LDC1,
                                wmma::mem_row_major);
    __syncthreads();

    // epilogue: scale by dinv, convert fp16, write. 2 threads/row, 64 cols each.
    {
        int r = tid >> 1, seg = tid & 1;
        int gr = rowBase + r;
        if (gr < N_NODES) {
            float di = __ldg(&g_dinv[gr]);
            const float* cr = &C_f[r * LDC1 + seg * 64];
            __half* hp = g_Hs + (size_t)gr * HID + seg * 64;
#pragma unroll
            for (int q = 0; q < 8; q++) {
                float4 v0 = *(const float4*)(cr + q * 8);
                float4 v1 = *(const float4*)(cr + q * 8 + 4);
                uint4 o;
                o.x = h2u(v0.x * di, v0.y * di);
                o.y = h2u(v0.z * di, v0.w * di);
                o.z = h2u(v1.x * di, v1.y * di);
                o.w = h2u(v1.z * di, v1.w * di);
                *(uint4*)(hp + q * 8) = o;
            }
        }
    }
}

// ---------------- layer-1 aggregate + relu + bias -> x1 (fp16) ----------------
// HALF-WARP per node; lane covers 8 cols via one uint4 (16B) per gather
__global__ void k_agg1(const float* __restrict__ b1) {
    int gw = (blockIdx.x * blockDim.x + threadIdx.x) >> 4;   // node
    if (gw >= N_NODES) return;
    const int l = threadIdx.x & 15;                          // 0..15, cols l*8..+7
    const uint4* hs = (const uint4*)g_Hs;     // row stride = 16 uint4

    float acc[8];
    {
        uint4 sv = __ldg(hs + (size_t)gw * 16 + l);   // self loop
        float2 p0 = u2f(sv.x), p1 = u2f(sv.y), p2 = u2f(sv.z), p3 = u2f(sv.w);
        acc[0] = p0.x; acc[1] = p0.y; acc[2] = p1.x; acc[3] = p1.y;
        acc[4] = p2.x; acc[5] = p2.y; acc[6] = p3.x; acc[7] = p3.y;
    }

    int beg = __ldg(&g_rowptr[gw]);
    int end = beg + __ldg(&g_cnt[gw]);
    int i = beg;
    for (; i + 4 <= end; i += 4) {
        int s0 = __ldg(g_adj + i),     s1 = __ldg(g_adj + i + 1);
        int s2 = __ldg(g_adj + i + 2), s3 = __ldg(g_adj + i + 3);
        uint4 v0 = __ldg(hs + (size_t)s0 * 16 + l);
        uint4 v1 = __ldg(hs + (size_t)s1 * 16 + l);
        uint4 v2 = __ldg(hs + (size_t)s2 * 16 + l);
        uint4 v3 = __ldg(hs + (size_t)s3 * 16 + l);
        acc8(acc, v0); acc8(acc, v1); acc8(acc, v2); acc8(acc, v3);
    }
    for (; i < end; i++) {
        int s = __ldg(g_adj + i);
        uint4 v = __ldg(hs + (size_t)s * 16 + l);
        acc8(acc, v);
    }
    float di = __ldg(&g_dinv[gw]);
    float4 bv0 = __ldg((const float4*)b1 + l * 2);
    float4 bv1 = __ldg((const float4*)b1 + l * 2 + 1);
    float r0 = fmaxf(fmaf(di, acc[0], bv0.x), 0.0f);
    float r1 = fmaxf(fmaf(di, acc[1], bv0.y), 0.0f);
    float r2 = fmaxf(fmaf(di, acc[2], bv0.z), 0.0f);
    float r3 = fmaxf(fmaf(di, acc[3], bv0.w), 0.0f);
    float r4 = fmaxf(fmaf(di, acc[4], bv1.x), 0.0f);
    float r5 = fmaxf(fmaf(di, acc[5], bv1.y), 0.0f);
    float r6 = fmaxf(fmaf(di, acc[6], bv1.z), 0.0f);
    float r7 = fmaxf(fmaf(di, acc[7], bv1.w), 0.0f);
    uint4 o;
    o.x = h2u(r0, r1);
    o.y = h2u(r2, r3);
    o.z = h2u(r4, r5);
    o.w = h2u(r6, r7);
    ((uint4*)g_X1h)[(size_t)gw * 16 + l] = o;
}

// ---------------- layer-2 GEMM (tensor cores): Hs2 = dinv * (x1 @ W2), fp16 out
#define LDA2 136
#define LDB2 72
#define LDC2 68
__global__ __launch_bounds__(256)
void k_gemm2_tc(const float* __restrict__ W2) {
    extern __shared__ char dynsmem[];
    __half* A_h = (__half*)dynsmem;                 // [128][136]
    __half* B_h = A_h + 128 * LDA2;                 // [128][72]
    float*  C_f = (float*)dynsmem;                  // [128][68] (reuse)

    const int tid  = threadIdx.x;
    const int warp = tid >> 5;
    const int rowBase = blockIdx.x * 128;

    // fill B: W2 fp32 -> fp16 (128x64)
    for (int idx = tid; idx < 128 * 32; idx += 256) {
        int k = idx >> 5, n2 = idx & 31;
        float2 w = *(const float2*)&W2[k * RPR + n2 * 2];
        *(unsigned int*)&B_h[k * LDB2 + n2 * 2] = h2u(w.x, w.y);
    }
    // fill A: X1h fp16 direct copy (uint4 = 8 halfs)
    for (int idx = tid; idx < 128 * 16; idx += 256) {
        int r = idx >> 4, q = idx & 15;
        int gr = rowBase + r;
        uint4 v = make_uint4(0, 0, 0, 0);
        if (gr < N_NODES)
            v = *(const uint4*)&g_X1h[(size_t)gr * HID + q * 8];
        *(uint4*)&A_h[r * LDA2 + q * 8] = v;
    }
    __syncthreads();

    wmma::fragment<wmma::accumulator, 16, 16, 16, float> acc[4];
#pragma unroll
    for (int n = 0; n < 4; n++) wmma::fill_fragment(acc[n], 0.0f);

#pragma unroll
    for (int k = 0; k < 8; k++) {
        wmma::fragment<wmma::matrix_a, 16, 16, 16, __half, wmma::row_major> a;
        wmma::load_matrix_sync(a, &A_h[warp * 16 * LDA2 + k * 16], LDA2);
#pragma unroll
        for (int n = 0; n < 4; n++) {
            wmma::fragment<wmma::matrix_b, 16, 16, 16, __half, wmma::row_major> b;
            wmma::load_matrix_sync(b, &B_h[k * 16 * LDB2 + n * 16], LDB2);
            wmma::mma_sync(acc[n], a, b, acc[n]);
        }
    }
    __syncthreads();

#pragma unroll
    for (int n = 0; n < 4; n++)
        wmma::store_matrix_sync(&C_f[warp * 16 * LDC2 + n * 16], acc[n], LDC2,
                                wmma::mem_row_major);
    __syncthreads();

    // epilogue: 2 threads/row, 32 cols each
    {
        int r = tid >> 1, seg = tid & 1;
        int gr = rowBase + r;
        if (gr < N_NODES) {
            float di = __ldg(&g_dinv[gr]);
            const float* cr = &C_f[r * LDC2 + seg * 32];
            __half* hp = g_Hs2 + (size_t)gr * RPR + seg * 32;
#pragma unroll
            for (int q = 0; q < 4; q++) {
                float4 v0 = *(const float4*)(cr + q * 8);
                float4 v1 = *(const float4*)(cr + q * 8 + 4);
                uint4 o;
                o.x = h2u(v0.x * di, v0.y * di);
                o.y = h2u(v0.z * di, v0.w * di);
                o.z = h2u(v1.x * di, v1.y * di);
                o.w = h2u(v1.z * di, v1.w * di);
                *(uint4*)(hp + q * 8) = o;
            }
        }
    }
}

// ---------------- layer-2 aggregate + bias -> out ----------------
// 8-LANE group per node; lane covers 8 cols via one uint4 (16B) per gather
__global__ void k_agg2(const float* __restrict__ b2, float* __restrict__ out) {
    int gh = (blockIdx.x * blockDim.x + threadIdx.x) >> 3;   // node
    if (gh >= N_NODES) return;
    const int l = threadIdx.x & 7;                           // 0..7, cols l*8..+7
    const uint4* hs = (const uint4*)g_Hs2;    // row stride = 8 uint4

    float acc[8];
    {
        uint4 sv = __ldg(hs + (size_t)gh * 8 + l);   // self loop
        float2 p0 = u2f(sv.x), p1 = u2f(sv.y), p2 = u2f(sv.z), p3 = u2f(sv.w);
        acc[0] = p0.x; acc[1] = p0.y; acc[2] = p1.x; acc[3] = p1.y;
        acc[4] = p2.x; acc[5] = p2.y; acc[6] = p3.x; acc[7] = p3.y;
    }

    int beg = __ldg(&g_rowptr[gh]);
    int end = beg + __ldg(&g_cnt[gh]);
    int i = beg;
    for (; i + 4 <= end; i += 4) {
        int s0 = __ldg(g_adj + i),     s1 = __ldg(g_adj + i + 1);
        int s2 = __ldg(g_adj + i + 2), s3 = __ldg(g_adj + i + 3);
        uint4 v0 = __ldg(hs + (size_t)s0 * 8 + l);
        uint4 v1 = __ldg(hs + (size_t)s1 * 8 + l);
        uint4 v2 = __ldg(hs + (size_t)s2 * 8 + l);
        uint4 v3 = __ldg(hs + (size_t)s3 * 8 + l);
        acc8(acc, v0); acc8(acc, v1); acc8(acc, v2); acc8(acc, v3);
    }
    for (; i < end; i++) {
        int s = __ldg(g_adj + i);
        uint4 v = __ldg(hs + (size_t)s * 8 + l);
        acc8(acc, v);
    }
    float di = __ldg(&g_dinv[gh]);
    float4 bv0 = __ldg((const float4*)b2 + l * 2);
    float4 bv1 = __ldg((const float4*)b2 + l * 2 + 1);
    float* op = out + (size_t)gh * RPR + l * 8;
    *(float4*)(op) = make_float4(fmaf(di, acc[0], bv0.x), fmaf(di, acc[1], bv0.y),
                                 fmaf(di, acc[2], bv0.z), fmaf(di, acc[3], bv0.w));
    *(float4*)(op + 4) = make_float4(fmaf(di, acc[4], bv1.x), fmaf(di, acc[5], bv1.y),
                                     fmaf(di, acc[6], bv1.z), fmaf(di, acc[7], bv1.w));
}

// ---------------- launch ----------------
#define SMEM_GEMM1 (2 * 128 * LDA1 * 2)                 // 69632 B
#define SMEM_GEMM2 (128 * LDA2 * 2 + 128 * LDB2 * 2)    // 53248 B

extern "C" void kernel_launch(void* const* d_in, const int* in_sizes, int n_in,
                              void* d_out, int out_size) {
    const int*   edge = (const int*)d_in[0];     // [2, E]: src row, dst row
    const float* x    = (const float*)d_in[1];   // [N, 128]
    const float* W1   = (const float*)d_in[2];   // [128, 128]
    const float* b1   = (const float*)d_in[3];   // [128]
    const float* W2   = (const float*)d_in[4];   // [128, 64]
    const float* b2   = (const float*)d_in[5];   // [64]
    float* out = (float*)d_out;                  // [N, 64]

    const int* src = edge;
    const int* dst = edge + N_EDGES;

    cudaFuncSetAttribute(k_gemm1_tc, cudaFuncAttributeMaxDynamicSharedMemorySize,
                         SMEM_GEMM1);
    cudaFuncSetAttribute(k_gemm2_tc, cudaFuncAttributeMaxDynamicSharedMemorySize,
                         SMEM_GEMM2);

    // CSR build (+ degree/dinv); fill is atomic-free (rank captured in hist)
    k_zero<<<SCAN_BLOCKS, 256>>>();
    k_hist<<<2048, 256>>>(dst);
    k_scan<<<SCAN_BLOCKS, 256>>>();
    k_fill<<<2048, 256>>>(src, dst);

    // layer 1
    k_gemm1_tc<<<(N_NODES + 127) / 128, 256, SMEM_GEMM1>>>(x, W1);
    k_agg1<<<(N_NODES * 16 + 255) / 256, 256>>>(b1);

    // layer 2
    k_gemm2_tc<<<(N_NODES + 127) / 128, 256, SMEM_GEMM2>>>(W2);
    k_agg2<<<(N_NODES * 8 + 255) / 256, 256>>>(b2, out);
}